// round 6
// baseline (speedup 1.0000x reference)
#include <cuda_runtime.h>
#include <math_constants.h>

#define H_IN   256
#define W_IN   256
#define H_OUT  128
#define W_OUT  128
#define NEG_INF (-CUDART_INF_F)

// Per-row lane data. e0..e2 are edge-patch values (disjoint lane usage):
//   lane 0  (right-half warp): e0=col cb-3, e1=cb-2, e2=cb-1
//   lane 31 (left-half  warp): e0=col cb+4, e1=cb+5
struct Row { float4 v; float e0, e1, e2; };

__device__ __forceinline__ Row ldrow(const float* __restrict__ fp, int r, int cb,
                                     bool ldL, bool ldR)
{
    Row x;
    x.v  = make_float4(NEG_INF, NEG_INF, NEG_INF, NEG_INF);
    x.e0 = NEG_INF; x.e1 = NEG_INF; x.e2 = NEG_INF;
    if ((unsigned)r < (unsigned)H_IN) {
        const float* rp = fp + r * W_IN;
        x.v = *(const float4*)(rp + cb);
        if (ldL) {
            x.e0 = rp[cb - 3];
            float2 q = *(const float2*)(rp + cb - 2);
            x.e1 = q.x; x.e2 = q.y;
        }
        if (ldR) {
            float2 q = *(const float2*)(rp + cb + 4);
            x.e0 = q.x; x.e1 = q.y;
        }
    }
    return x;
}

// Horizontal 7-tap max-plus: lane owns input cols cb..cb+3, outputs cols
// cb/2 (center v.x) and cb/2+1 (center v.z). Symmetric weights.
__device__ __forceinline__ float2 hmax(const Row& x, int lane,
                                       float h1, float h2, float h3)
{
    float m3 = __shfl_up_sync(0xffffffffu, x.v.y, 1);   // col cb-3
    float m2 = __shfl_up_sync(0xffffffffu, x.v.z, 1);   // col cb-2
    float m1 = __shfl_up_sync(0xffffffffu, x.v.w, 1);   // col cb-1
    float p4 = __shfl_down_sync(0xffffffffu, x.v.x, 1); // col cb+4
    float p5 = __shfl_down_sync(0xffffffffu, x.v.y, 1); // col cb+5
    if (lane == 0)  { m3 = x.e0; m2 = x.e1; m1 = x.e2; }
    if (lane == 31) { p4 = x.e0; p5 = x.e1; }

    float gA = fmaxf(fmaxf(x.v.x,                fmaxf(m2,    x.v.z) + h2),
                     fmaxf(fmaxf(m1,    x.v.y) + h1, fmaxf(m3, x.v.w) + h3));
    float gB = fmaxf(fmaxf(x.v.z,                fmaxf(x.v.x, p4)    + h2),
                     fmaxf(fmaxf(x.v.y, x.v.w) + h1, fmaxf(m1, p5)    + h3));
    return make_float2(gA, gB);
}

__device__ __forceinline__ float2 vmax(const float2* ring, int s0,
                                       float h1, float h2, float h3)
{
    float2 c  = ring[s0 & 7];
    float2 a1 = ring[(s0 + 7) & 7], b1 = ring[(s0 + 1) & 7];
    float2 a2 = ring[(s0 + 6) & 7], b2 = ring[(s0 + 2) & 7];
    float2 a3 = ring[(s0 + 5) & 7], b3 = ring[(s0 + 3) & 7];
    float2 o;
    o.x = fmaxf(fmaxf(c.x, fmaxf(a1.x, b1.x) + h1),
                fmaxf(fmaxf(a2.x, b2.x) + h2, fmaxf(a3.x, b3.x) + h3));
    o.y = fmaxf(fmaxf(c.y, fmaxf(a1.y, b1.y) + h1),
                fmaxf(fmaxf(a2.y, b2.y) + h2, fmaxf(a3.y, b3.y) + h3));
    return o;
}

__global__ __launch_bounds__(128, 6)
void parabolic_pool_kernel(const float* __restrict__ f,
                           const float* __restrict__ tptr,
                           float* __restrict__ out)
{
    // warps of a block share a plane: (col-half, row-strip) per warp
    const int gw    = blockIdx.x * 4 + (threadIdx.x >> 5);
    const int lane  = threadIdx.x & 31;
    const int plane = gw >> 2;
    const int c0    = ((gw >> 1) & 1) * 128;   // input col base of this warp
    const int i0    = (gw & 1) * 64;           // output row strip origin
    const int cb    = c0 + 4 * lane;           // this lane's input col base

    const bool ldL = (lane == 0)  && (c0 != 0);
    const bool ldR = (lane == 31) && (c0 == 0);

    const float* __restrict__ fp = f + (size_t)plane * (H_IN * W_IN);
    float* __restrict__ op = out + (size_t)plane * (H_OUT * W_OUT)
                                 + (size_t)i0 * W_OUT + c0 / 2 + 2 * lane;

    const float inv4t = 0.25f / tptr[0];
    const float h1 = -1.0f * inv4t;
    const float h2 = -4.0f * inv4t;
    const float h3 = -9.0f * inv4t;

    // ring[R & 7] = horizontal max-plus of input row R
    float2 ring[8];

    // ---- prologue: input rows 2*i0-3 .. 2*i0+3 ----
#pragma unroll
    for (int k = 0; k < 7; ++k) {
        Row x = ldrow(fp, 2 * i0 - 3 + k, cb, ldL, ldR);
        ring[(k + 5) & 7] = hmax(x, lane, h1, h2, h3);
    }

    // 4-row prefetch pipeline: rows 2*i0+4 .. 2*i0+7 in flight
    Row pv0 = ldrow(fp, 2 * i0 + 4, cb, ldL, ldR);
    Row pv1 = ldrow(fp, 2 * i0 + 5, cb, ldL, ldR);
    Row pv2 = ldrow(fp, 2 * i0 + 6, cb, ldL, ldR);
    Row pv3 = ldrow(fp, 2 * i0 + 7, cb, ldL, ldR);

    // ---- body: 64 output rows, unrolled x4 (static ring/pv indices) ----
    for (int ib = 0; ib < 16; ++ib) {
#pragma unroll
        for (int ip = 0; ip < 4; ++ip) {
            const int i = ib * 4 + ip;                  // local output row

            // vertical max-plus (center input row 2*(i0+i) -> slot 2*ip) + store
            float2 o = vmax(ring, 2 * ip, h1, h2, h3);
            *(float2*)(op + i * W_OUT) = o;

            // consume the row pair loaded TWO iterations ago; refill its slot
            const int rn = 2 * (i0 + i) + 8;
            Row a, b;
            if ((ip & 1) == 0) {
                a = pv0; b = pv1;
                pv0 = ldrow(fp, rn,     cb, ldL, ldR);
                pv1 = ldrow(fp, rn + 1, cb, ldL, ldR);
            } else {
                a = pv2; b = pv3;
                pv2 = ldrow(fp, rn,     cb, ldL, ldR);
                pv3 = ldrow(fp, rn + 1, cb, ldL, ldR);
            }
            ring[(2 * ip + 4) & 7] = hmax(a, lane, h1, h2, h3);
            ring[(2 * ip + 5) & 7] = hmax(b, lane, h1, h2, h3);
        }
    }
}

extern "C" void kernel_launch(void* const* d_in, const int* in_sizes, int n_in,
                              void* d_out, int out_size)
{
    const float* f = (const float*)d_in[0];
    const float* t = (const float*)d_in[1];
    float* out = (float*)d_out;

    // 2048 planes x 2 col-halves x 2 row-strips = 8192 warps = 2048 blocks x 128
    parabolic_pool_kernel<<<2048, 128>>>(f, t, out);
}

// round 7
// speedup vs baseline: 1.5854x; 1.5854x over previous
#include <cuda_runtime.h>
#include <math_constants.h>

#define H_IN   256
#define W_IN   256
#define H_OUT  128
#define W_OUT  128
#define NEG_INF (-CUDART_INF_F)

// One lane owns 8 input cols: a = cols 8l..8l+3, b = cols 8l+4..8l+7.
// A warp spans the full 256-col row -> shuffle edges are true image borders,
// so there are NO edge-patch loads at all.
struct Row8 { float4 a, b; };

__device__ __forceinline__ Row8 ldrow(const float* __restrict__ fp, int r, int c)
{
    Row8 x;
    x.a = make_float4(NEG_INF, NEG_INF, NEG_INF, NEG_INF);
    x.b = x.a;
    if ((unsigned)r < (unsigned)H_IN) {
        const float* rp = fp + r * W_IN + c;
        x.a = *(const float4*)(rp);
        x.b = *(const float4*)(rp + 4);
    }
    return x;
}

// Horizontal 7-tap max-plus: 4 output cols (centers 8l, 8l+2, 8l+4, 8l+6).
// Symmetric weights h[o] = -o^2/(4t): pair-max then single add.
__device__ __forceinline__ float4 hmax(const Row8& x, int lane,
                                       float h1, float h2, float h3)
{
    float m3 = __shfl_up_sync(0xffffffffu, x.b.y, 1);   // col 8l-3
    float m2 = __shfl_up_sync(0xffffffffu, x.b.z, 1);   // col 8l-2
    float m1 = __shfl_up_sync(0xffffffffu, x.b.w, 1);   // col 8l-1
    float p8 = __shfl_down_sync(0xffffffffu, x.a.x, 1); // col 8l+8
    float p9 = __shfl_down_sync(0xffffffffu, x.a.y, 1); // col 8l+9
    if (lane == 0)  { m3 = NEG_INF; m2 = NEG_INF; m1 = NEG_INF; }
    if (lane == 31) { p8 = NEG_INF; p9 = NEG_INF; }

    float4 g;
    g.x = fmaxf(fmaxf(x.a.x,                    fmaxf(m1,    x.a.y) + h1),
                fmaxf(fmaxf(m2,    x.a.z) + h2, fmaxf(m3,    x.a.w) + h3));
    g.y = fmaxf(fmaxf(x.a.z,                    fmaxf(x.a.y, x.a.w) + h1),
                fmaxf(fmaxf(x.a.x, x.b.x) + h2, fmaxf(m1,    x.b.y) + h3));
    g.z = fmaxf(fmaxf(x.b.x,                    fmaxf(x.a.w, x.b.y) + h1),
                fmaxf(fmaxf(x.a.z, x.b.z) + h2, fmaxf(x.a.y, x.b.w) + h3));
    g.w = fmaxf(fmaxf(x.b.z,                    fmaxf(x.b.y, x.b.w) + h1),
                fmaxf(fmaxf(x.b.x, p8)    + h2, fmaxf(x.a.w, p9)    + h3));
    return g;
}

__device__ __forceinline__ float4 vmax(const float4* ring, int s0,
                                       float h1, float h2, float h3)
{
    float4 c  = ring[s0 & 7];
    float4 a1 = ring[(s0 + 7) & 7], b1 = ring[(s0 + 1) & 7];
    float4 a2 = ring[(s0 + 6) & 7], b2 = ring[(s0 + 2) & 7];
    float4 a3 = ring[(s0 + 5) & 7], b3 = ring[(s0 + 3) & 7];
    float4 o;
    o.x = fmaxf(fmaxf(c.x, fmaxf(a1.x, b1.x) + h1),
                fmaxf(fmaxf(a2.x, b2.x) + h2, fmaxf(a3.x, b3.x) + h3));
    o.y = fmaxf(fmaxf(c.y, fmaxf(a1.y, b1.y) + h1),
                fmaxf(fmaxf(a2.y, b2.y) + h2, fmaxf(a3.y, b3.y) + h3));
    o.z = fmaxf(fmaxf(c.z, fmaxf(a1.z, b1.z) + h1),
                fmaxf(fmaxf(a2.z, b2.z) + h2, fmaxf(a3.z, b3.z) + h3));
    o.w = fmaxf(fmaxf(c.w, fmaxf(a1.w, b1.w) + h1),
                fmaxf(fmaxf(a2.w, b2.w) + h2, fmaxf(a3.w, b3.w) + h3));
    return o;
}

__global__ __launch_bounds__(128)
void parabolic_pool_kernel(const float* __restrict__ f,
                           const float* __restrict__ tptr,
                           float* __restrict__ out)
{
    // one warp per (plane, 64-row strip); warp spans the full 256-col width
    const int gw    = blockIdx.x * 4 + (threadIdx.x >> 5);   // 0..4095
    const int lane  = threadIdx.x & 31;
    const int plane = gw >> 1;
    const int i0    = (gw & 1) * 64;             // output row strip origin
    const int cb    = 8 * lane;                  // lane's input col base

    const float* __restrict__ fp = f + (size_t)plane * (H_IN * W_IN);
    float* __restrict__ op = out + (size_t)plane * (H_OUT * W_OUT)
                                 + (size_t)i0 * W_OUT + 4 * lane;

    const float inv4t = 0.25f / tptr[0];
    const float h1 = -1.0f * inv4t;
    const float h2 = -4.0f * inv4t;
    const float h3 = -9.0f * inv4t;

    // ring[R & 7] = horizontal max-plus of input row R
    float4 ring[8];

    // ---- prologue: input rows 2*i0-3 .. 2*i0+3 ----
#pragma unroll
    for (int k = 0; k < 7; ++k) {
        Row8 x = ldrow(fp, 2 * i0 - 3 + k, cb);
        ring[(k + 5) & 7] = hmax(x, lane, h1, h2, h3);
    }

    // 2-row prefetch: rows 2*i0+4, 2*i0+5 (always in range)
    Row8 pva = ldrow(fp, 2 * i0 + 4, cb);
    Row8 pvb = ldrow(fp, 2 * i0 + 5, cb);

    // ---- body: 64 output rows, unrolled x4 (static ring indices) ----
    for (int ib = 0; ib < 16; ++ib) {
#pragma unroll
        for (int ip = 0; ip < 4; ++ip) {
            const int i = ib * 4 + ip;                  // local output row

            // vertical max-plus (center input row 2*(i0+i) -> slot 2*ip) + store
            float4 o = vmax(ring, 2 * ip, h1, h2, h3);
            *(float4*)(op + i * W_OUT) = o;

            // rotate prefetched rows into the pipeline, issue next loads
            Row8 na = pva, nb = pvb;
            const int rn = 2 * (i0 + i) + 6;
            pva = ldrow(fp, rn,     cb);
            pvb = ldrow(fp, rn + 1, cb);

            ring[(2 * ip + 4) & 7] = hmax(na, lane, h1, h2, h3);
            ring[(2 * ip + 5) & 7] = hmax(nb, lane, h1, h2, h3);
        }
    }
}

extern "C" void kernel_launch(void* const* d_in, const int* in_sizes, int n_in,
                              void* d_out, int out_size)
{
    const float* f = (const float*)d_in[0];
    const float* t = (const float*)d_in[1];
    float* out = (float*)d_out;

    // 2048 planes x 2 row-strips = 4096 warps = 1024 blocks x 4 warps
    parabolic_pool_kernel<<<1024, 128>>>(f, t, out);
}